// round 2
// baseline (speedup 1.0000x reference)
#include <cuda_runtime.h>
#include <math.h>

#define N_NODES 100000
#define N_EDGES 1000000
#define D_NODE 64
#define D_EDGE 16
#define NUM_PAR 80
#define HIDDEN 160

// Scratch (allocation-free rule): collapsed weights + node projections.
__device__ float g_w[NUM_PAR];
__device__ float g_c;
__device__ float g_p[N_NODES];
__device__ int   g_is64;   // 1 if edge_index is int64, 0 if int32

// ---------------------------------------------------------------------------
// Kernel 1: collapse the two linear layers + probe edge_index dtype.
//   w[i] = sum_j W1[i, j] * W2[j]     (W1 [80,160] row-major, W2 [160])
//   c    = sum_j b1[j] * W2[j] + b2[0]
// Dtype probe: interpret first 64 entries as int64; all in [0, N_NODES)
// only if truly int64 (int32 data would need 64 zero high-words: P ~ 1e-320).
// ---------------------------------------------------------------------------
__global__ void collapse_weights_kernel(const float* __restrict__ W1,
                                        const float* __restrict__ b1,
                                        const float* __restrict__ W2,
                                        const float* __restrict__ b2,
                                        const long long* __restrict__ ei64) {
    int i = threadIdx.x;
    if (i < NUM_PAR) {
        double s = 0.0;
        const float* row = W1 + i * HIDDEN;
        #pragma unroll 8
        for (int j = 0; j < HIDDEN; j++) s += (double)row[j] * (double)W2[j];
        g_w[i] = (float)s;
    }
    if (i == NUM_PAR) {
        double s = (double)b2[0];
        for (int j = 0; j < HIDDEN; j++) s += (double)b1[j] * (double)W2[j];
        g_c = (float)s;
    }
    if (i == NUM_PAR + 1) {
        int ok = 1;
        for (int j = 0; j < 64; j++) {
            long long v = ei64[j];
            if (v < 0 || v >= N_NODES) { ok = 0; break; }
        }
        g_is64 = ok;
    }
}

// ---------------------------------------------------------------------------
// Kernel 2: node projections p[n] = dot(x[n], w[0:64]).
// One warp per node: each lane loads a float2 (coalesced 256B per warp),
// then a 32-wide shuffle reduction.
// ---------------------------------------------------------------------------
__global__ void node_proj_kernel(const float* __restrict__ x) {
    __shared__ float sw[D_NODE];
    int t = threadIdx.x;
    if (t < D_NODE) sw[t] = g_w[t];
    __syncthreads();

    int warp = t >> 5;
    int lane = t & 31;
    int node = blockIdx.x * 8 + warp;   // 8 warps/block
    if (node >= N_NODES) return;

    float2 v = __ldg(((const float2*)x) + (size_t)node * 32 + lane);
    float s = v.x * sw[lane * 2] + v.y * sw[lane * 2 + 1];

    #pragma unroll
    for (int o = 16; o > 0; o >>= 1) s += __shfl_xor_sync(0xFFFFFFFFu, s, o);

    if (lane == 0) g_p[node] = s;
}

// ---------------------------------------------------------------------------
// Kernel 3: per-edge: gather p[src]+p[dst], dot edge_attr with w[64:80],
// sigmoid. One thread per edge; edge_attr row = 64B = 4x float4, coalesced.
// p[] is 400KB -> random gathers hit L2. Index dtype selected via g_is64
// (uniform branch, decided once per launch).
// ---------------------------------------------------------------------------
__global__ void edge_kernel(const void* __restrict__ ei_raw,
                            const float* __restrict__ ea,
                            float* __restrict__ out) {
    __shared__ float sw[D_EDGE];
    __shared__ float sc;
    int t = threadIdx.x;
    if (t < D_EDGE) sw[t] = g_w[D_NODE + t];
    if (t == D_EDGE) sc = g_c;
    __syncthreads();

    int e = blockIdx.x * blockDim.x + t;
    if (e >= N_EDGES) return;

    int s, d;
    if (g_is64) {
        const long long* ei = (const long long*)ei_raw;
        s = (int)ei[e];
        d = (int)ei[(size_t)N_EDGES + e];
    } else {
        const int* ei = (const int*)ei_raw;
        s = ei[e];
        d = ei[(size_t)N_EDGES + e];
    }

    float z = g_p[s] + g_p[d] + sc;

    const float4* a = (const float4*)(ea + (size_t)e * D_EDGE);
    float4 a0 = a[0], a1 = a[1], a2 = a[2], a3 = a[3];
    z += a0.x * sw[0]  + a0.y * sw[1]  + a0.z * sw[2]  + a0.w * sw[3];
    z += a1.x * sw[4]  + a1.y * sw[5]  + a1.z * sw[6]  + a1.w * sw[7];
    z += a2.x * sw[8]  + a2.y * sw[9]  + a2.z * sw[10] + a2.w * sw[11];
    z += a3.x * sw[12] + a3.y * sw[13] + a3.z * sw[14] + a3.w * sw[15];

    out[e] = 1.0f / (1.0f + expf(-z));
}

extern "C" void kernel_launch(void* const* d_in, const int* in_sizes, int n_in,
                              void* d_out, int out_size) {
    // metadata order: x, edge_index, edge_attr, W1, b1, W2, b2
    const float*     x  = (const float*)d_in[0];
    const void*      ei = d_in[1];
    const float*     ea = (const float*)d_in[2];
    const float*     W1 = (const float*)d_in[3];
    const float*     b1 = (const float*)d_in[4];
    const float*     W2 = (const float*)d_in[5];
    const float*     b2 = (const float*)d_in[6];
    float* out = (float*)d_out;

    collapse_weights_kernel<<<1, 128>>>(W1, b1, W2, b2, (const long long*)ei);

    // 8 nodes per block (8 warps), 256 threads
    int nblocks = (N_NODES + 7) / 8;
    node_proj_kernel<<<nblocks, 256>>>(x);

    int eblocks = (N_EDGES + 255) / 256;
    edge_kernel<<<eblocks, 256>>>(ei, ea, out);
}

// round 3
// speedup vs baseline: 1.0870x; 1.0870x over previous
#include <cuda_runtime.h>
#include <math.h>

#define N_NODES 100000
#define N_EDGES 1000000
#define D_NODE 64
#define D_EDGE 16
#define NUM_PAR 80
#define HIDDEN 160

// Scratch (allocation-free rule): collapsed weights + node projections.
__device__ float g_w[NUM_PAR];
__device__ float g_c;
__device__ float g_p[N_NODES];
__device__ int   g_is64;   // 1 if edge_index is int64, 0 if int32

// ---------------------------------------------------------------------------
// Kernel 1: collapse the two linear layers + probe edge_index dtype.
//   w[i] = sum_j W1[i,j] * W2[j]     (W1 [80,160] row-major, W2 [160])
//   c    = sum_j b1[j] * W2[j] + b2[0]
// All in fp32 (160-term sums: ~1e-6 rel err, tolerance is 1e-3).
// Probe is fully parallel: lanes 0..63 (warps 4-5) each test one int64 entry,
// combined with ballots -> one DRAM latency instead of 64 serial ones.
// ---------------------------------------------------------------------------
__global__ void collapse_weights_kernel(const float* __restrict__ W1,
                                        const float* __restrict__ b1,
                                        const float* __restrict__ W2,
                                        const float* __restrict__ b2,
                                        const long long* __restrict__ ei64) {
    __shared__ float sW2[HIDDEN];
    __shared__ int ok_lo, ok_hi;
    int t = threadIdx.x;   // 256 threads

    // Parallel dtype probe (warps 4,5 = threads 128..191) — issue loads first.
    if (t >= 128 && t < 192) {
        int j = t - 128;
        long long v = ei64[j];
        int in_range = (v >= 0 && v < N_NODES) ? 1 : 0;
        unsigned b = __ballot_sync(0xFFFFFFFFu, in_range);
        if ((t & 31) == 0) {
            if (t == 128) ok_lo = (b == 0xFFFFFFFFu);
            else          ok_hi = (b == 0xFFFFFFFFu);
        }
    }

    if (t < HIDDEN) sW2[t] = W2[t];
    __syncthreads();

    if (t < NUM_PAR) {
        float s = 0.f;
        const float* row = W1 + t * HIDDEN;
        #pragma unroll 8
        for (int j = 0; j < HIDDEN; j++) s = fmaf(row[j], sW2[j], s);
        g_w[t] = s;
    } else if (t == NUM_PAR) {
        float s = b2[0];
        #pragma unroll 8
        for (int j = 0; j < HIDDEN; j++) s = fmaf(b1[j], sW2[j], s);
        g_c = s;
    } else if (t == NUM_PAR + 1) {
        g_is64 = ok_lo & ok_hi;
    }
}

// ---------------------------------------------------------------------------
// Kernel 2: node projections p[n] = dot(x[n], w[0:64]).
// One warp per node: each lane loads a float2 (coalesced 256B per warp),
// then a 32-wide shuffle reduction. Pure bandwidth: 25.6MB read.
// ---------------------------------------------------------------------------
__global__ void node_proj_kernel(const float* __restrict__ x) {
    __shared__ float sw[D_NODE];
    int t = threadIdx.x;
    if (t < D_NODE) sw[t] = g_w[t];
    __syncthreads();

    int warp = t >> 5;
    int lane = t & 31;
    int node = blockIdx.x * 8 + warp;   // 8 warps/block
    if (node >= N_NODES) return;

    float2 v = __ldg(((const float2*)x) + (size_t)node * 32 + lane);
    float s = v.x * sw[lane * 2] + v.y * sw[lane * 2 + 1];

    #pragma unroll
    for (int o = 16; o > 0; o >>= 1) s += __shfl_xor_sync(0xFFFFFFFFu, s, o);

    if (lane == 0) g_p[node] = s;
}

// ---------------------------------------------------------------------------
// Kernel 3: per-edge: gather p[src]+p[dst], dot edge_attr with w[64:80],
// sigmoid. One thread per edge; edge_attr row = 64B = 4x float4, coalesced.
// p[] is 400KB -> random gathers hit L2. Index dtype selected via g_is64
// (uniform branch). ~76MB DRAM traffic total.
// ---------------------------------------------------------------------------
__global__ void edge_kernel(const void* __restrict__ ei_raw,
                            const float* __restrict__ ea,
                            float* __restrict__ out) {
    __shared__ float sw[D_EDGE];
    __shared__ float sc;
    int t = threadIdx.x;
    if (t < D_EDGE) sw[t] = g_w[D_NODE + t];
    if (t == D_EDGE) sc = g_c;
    __syncthreads();

    int e = blockIdx.x * blockDim.x + t;
    if (e >= N_EDGES) return;

    int s, d;
    if (g_is64) {
        const long long* ei = (const long long*)ei_raw;
        s = (int)ei[e];
        d = (int)ei[(size_t)N_EDGES + e];
    } else {
        const int* ei = (const int*)ei_raw;
        s = ei[e];
        d = ei[(size_t)N_EDGES + e];
    }

    float z = g_p[s] + g_p[d] + sc;

    const float4* a = (const float4*)(ea + (size_t)e * D_EDGE);
    float4 a0 = a[0], a1 = a[1], a2 = a[2], a3 = a[3];
    z += a0.x * sw[0]  + a0.y * sw[1]  + a0.z * sw[2]  + a0.w * sw[3];
    z += a1.x * sw[4]  + a1.y * sw[5]  + a1.z * sw[6]  + a1.w * sw[7];
    z += a2.x * sw[8]  + a2.y * sw[9]  + a2.z * sw[10] + a2.w * sw[11];
    z += a3.x * sw[12] + a3.y * sw[13] + a3.z * sw[14] + a3.w * sw[15];

    out[e] = 1.0f / (1.0f + __expf(-z));
}

extern "C" void kernel_launch(void* const* d_in, const int* in_sizes, int n_in,
                              void* d_out, int out_size) {
    // metadata order: x, edge_index, edge_attr, W1, b1, W2, b2
    const float*     x  = (const float*)d_in[0];
    const void*      ei = d_in[1];
    const float*     ea = (const float*)d_in[2];
    const float*     W1 = (const float*)d_in[3];
    const float*     b1 = (const float*)d_in[4];
    const float*     W2 = (const float*)d_in[5];
    const float*     b2 = (const float*)d_in[6];
    float* out = (float*)d_out;

    collapse_weights_kernel<<<1, 256>>>(W1, b1, W2, b2, (const long long*)ei);

    int nblocks = (N_NODES + 7) / 8;
    node_proj_kernel<<<nblocks, 256>>>(x);

    int eblocks = (N_EDGES + 255) / 256;
    edge_kernel<<<eblocks, 256>>>(ei, ea, out);
}

// round 4
// speedup vs baseline: 1.3865x; 1.2756x over previous
#include <cuda_runtime.h>
#include <math.h>

#define N_NODES 100000
#define N_EDGES 1000000
#define D_NODE 64
#define D_EDGE 16
#define NUM_PAR 80
#define HIDDEN 160

// Scratch (allocation-free rule): collapsed weights + node projections.
__device__ float g_w[NUM_PAR];
__device__ float g_c;
__device__ float g_p[N_NODES];
__device__ int   g_is64;   // 1 if edge_index is int64, 0 if int32

// ---------------------------------------------------------------------------
// Kernel 1: collapse the two linear layers + probe edge_index dtype.
//   w[i] = sum_j W1[i,j] * W2[j]   (W1 [80,160] row-major, W2 [160]);  c likewise.
// Latency-optimized: warp per 10 rows; lane l keeps W2[l+32k] in registers and
// issues all 50 W1 loads independently (coalesced) -> ~1 DRAM round-trip,
// then 10 shuffle reductions. Probe warp: 32 parallel int64 range checks.
// ---------------------------------------------------------------------------
__global__ void collapse_weights_kernel(const float* __restrict__ W1,
                                        const float* __restrict__ b1,
                                        const float* __restrict__ W2,
                                        const float* __restrict__ b2,
                                        const long long* __restrict__ ei64) {
    int t = threadIdx.x;          // 320 threads = 10 warps
    int warp = t >> 5;
    int lane = t & 31;

    if (warp < 8) {
        // 10 rows per warp; 5 j-strides per lane (160 = 5*32).
        float w2[5];
        #pragma unroll
        for (int k = 0; k < 5; k++) w2[k] = __ldg(W2 + lane + 32 * k);

        #pragma unroll
        for (int rr = 0; rr < 10; rr++) {
            int r = warp * 10 + rr;
            const float* row = W1 + r * HIDDEN;
            float s = 0.f;
            #pragma unroll
            for (int k = 0; k < 5; k++)
                s = fmaf(__ldg(row + lane + 32 * k), w2[k], s);
            #pragma unroll
            for (int o = 16; o > 0; o >>= 1)
                s += __shfl_xor_sync(0xFFFFFFFFu, s, o);
            if (lane == 0) g_w[r] = s;
        }
    } else if (warp == 8) {
        // Parallel dtype probe: one int64 entry per lane, one ballot.
        // int32 data read as int64 is in [0,N_NODES) only if the hi word is 0:
        // P(all 32 pass) ~ (1e-5)^32 — effectively impossible.
        long long v = ei64[lane];
        int ok = (v >= 0 && v < N_NODES) ? 1 : 0;
        unsigned b = __ballot_sync(0xFFFFFFFFu, ok);
        if (lane == 0) g_is64 = (b == 0xFFFFFFFFu) ? 1 : 0;
    } else {
        // Bias row: c = b1 . W2 + b2
        float s = 0.f;
        #pragma unroll
        for (int k = 0; k < 5; k++)
            s = fmaf(__ldg(b1 + lane + 32 * k), __ldg(W2 + lane + 32 * k), s);
        #pragma unroll
        for (int o = 16; o > 0; o >>= 1)
            s += __shfl_xor_sync(0xFFFFFFFFu, s, o);
        if (lane == 0) g_c = s + __ldg(b2);
    }
}

// ---------------------------------------------------------------------------
// Kernel 2: node projections p[n] = dot(x[n], w[0:64]).
// One warp per node: each lane loads a float2 (coalesced 256B per warp),
// then a 32-wide shuffle reduction. Pure bandwidth: 25.6MB read.
// ---------------------------------------------------------------------------
__global__ void node_proj_kernel(const float* __restrict__ x) {
    __shared__ float sw[D_NODE];
    int t = threadIdx.x;
    if (t < D_NODE) sw[t] = g_w[t];
    __syncthreads();

    int warp = t >> 5;
    int lane = t & 31;
    int node = blockIdx.x * 8 + warp;   // 8 warps/block
    if (node >= N_NODES) return;

    float2 v = __ldg(((const float2*)x) + (size_t)node * 32 + lane);
    float s = v.x * sw[lane * 2] + v.y * sw[lane * 2 + 1];

    #pragma unroll
    for (int o = 16; o > 0; o >>= 1) s += __shfl_xor_sync(0xFFFFFFFFu, s, o);

    if (lane == 0) g_p[node] = s;
}

// ---------------------------------------------------------------------------
// Kernel 3: per-edge: gather p[src]+p[dst], dot edge_attr with w[64:80],
// sigmoid. One thread per edge; edge_attr row = 64B = 4x float4, coalesced.
// p[] is 400KB -> random gathers hit L2. Index dtype selected via g_is64
// (uniform branch). ~76MB DRAM traffic total.
// ---------------------------------------------------------------------------
__global__ void edge_kernel(const void* __restrict__ ei_raw,
                            const float* __restrict__ ea,
                            float* __restrict__ out) {
    __shared__ float sw[D_EDGE];
    __shared__ float sc;
    int t = threadIdx.x;
    if (t < D_EDGE) sw[t] = g_w[D_NODE + t];
    if (t == D_EDGE) sc = g_c;
    __syncthreads();

    int e = blockIdx.x * blockDim.x + t;
    if (e >= N_EDGES) return;

    int s, d;
    if (g_is64) {
        const long long* ei = (const long long*)ei_raw;
        s = (int)ei[e];
        d = (int)ei[(size_t)N_EDGES + e];
    } else {
        const int* ei = (const int*)ei_raw;
        s = ei[e];
        d = ei[(size_t)N_EDGES + e];
    }

    float z = g_p[s] + g_p[d] + sc;

    const float4* a = (const float4*)(ea + (size_t)e * D_EDGE);
    float4 a0 = a[0], a1 = a[1], a2 = a[2], a3 = a[3];
    z += a0.x * sw[0]  + a0.y * sw[1]  + a0.z * sw[2]  + a0.w * sw[3];
    z += a1.x * sw[4]  + a1.y * sw[5]  + a1.z * sw[6]  + a1.w * sw[7];
    z += a2.x * sw[8]  + a2.y * sw[9]  + a2.z * sw[10] + a2.w * sw[11];
    z += a3.x * sw[12] + a3.y * sw[13] + a3.z * sw[14] + a3.w * sw[15];

    out[e] = 1.0f / (1.0f + __expf(-z));
}

extern "C" void kernel_launch(void* const* d_in, const int* in_sizes, int n_in,
                              void* d_out, int out_size) {
    // metadata order: x, edge_index, edge_attr, W1, b1, W2, b2
    const float*     x  = (const float*)d_in[0];
    const void*      ei = d_in[1];
    const float*     ea = (const float*)d_in[2];
    const float*     W1 = (const float*)d_in[3];
    const float*     b1 = (const float*)d_in[4];
    const float*     W2 = (const float*)d_in[5];
    const float*     b2 = (const float*)d_in[6];
    float* out = (float*)d_out;

    collapse_weights_kernel<<<1, 320>>>(W1, b1, W2, b2, (const long long*)ei);

    int nblocks = (N_NODES + 7) / 8;
    node_proj_kernel<<<nblocks, 256>>>(x);

    int eblocks = (N_EDGES + 255) / 256;
    edge_kernel<<<eblocks, 256>>>(ei, ea, out);
}

// round 5
// speedup vs baseline: 1.3889x; 1.0017x over previous
#include <cuda_runtime.h>
#include <math.h>

#define N_NODES 100000
#define N_EDGES 1000000
#define D_NODE 64
#define D_EDGE 16
#define NUM_PAR 80
#define HIDDEN 160

#define NODE_BLOCKS 592
#define NODE_THREADS 512          // 16 warps
#define EDGE_THREADS 256
#define EDGE_EPT 4                // edges per thread (block-strided)
#define EDGE_BLOCKS ((N_EDGES + EDGE_THREADS * EDGE_EPT - 1) / (EDGE_THREADS * EDGE_EPT))

// Scratch (allocation-free rule): node projections.
__device__ float g_p[N_NODES];

// Warp-cooperative collapsed weight for one row r of W1:
//   w[r] = sum_j W1[r,j] * W2[j], lane-parallel over j (5 strides of 32).
__device__ __forceinline__ float collapse_row(const float* __restrict__ W1,
                                              const float* __restrict__ w2reg,
                                              int r, int lane) {
    const float* row = W1 + r * HIDDEN;
    float s = 0.f;
    #pragma unroll
    for (int k = 0; k < 5; k++)
        s = fmaf(__ldg(row + lane + 32 * k), w2reg[k], s);
    #pragma unroll
    for (int o = 16; o > 0; o >>= 1)
        s += __shfl_xor_sync(0xFFFFFFFFu, s, o);
    return s;   // valid in all lanes
}

// ---------------------------------------------------------------------------
// Kernel A: node projections p[n] = dot(x[n], w[0:64]).
// Each block first recomputes w[0:64] (warps 0-7, 8 rows each; L2-resident
// after wave 1), then grid-strides: one warp per node, lane reads float2
// (coalesced 256B/warp), shuffle reduction.
// ---------------------------------------------------------------------------
__global__ __launch_bounds__(NODE_THREADS)
void node_kernel(const float* __restrict__ x,
                 const float* __restrict__ W1,
                 const float* __restrict__ W2) {
    __shared__ float sw[D_NODE];
    int t = threadIdx.x;
    int warp = t >> 5;
    int lane = t & 31;

    if (warp < 8) {
        float w2[5];
        #pragma unroll
        for (int k = 0; k < 5; k++) w2[k] = __ldg(W2 + lane + 32 * k);
        #pragma unroll
        for (int rr = 0; rr < 8; rr++) {
            int r = warp * 8 + rr;
            float s = collapse_row(W1, w2, r, lane);
            if (lane == 0) sw[r] = s;
        }
    }
    __syncthreads();

    // Per-lane register copy (avoids stride-2 smem bank conflicts in the loop).
    float rw0 = sw[lane * 2];
    float rw1 = sw[lane * 2 + 1];

    const int nwarps = NODE_BLOCKS * (NODE_THREADS / 32);
    for (int node = blockIdx.x * (NODE_THREADS / 32) + warp;
         node < N_NODES; node += nwarps) {
        float2 v = __ldg(((const float2*)x) + (size_t)node * 32 + lane);
        float s = fmaf(v.x, rw0, v.y * rw1);
        #pragma unroll
        for (int o = 16; o > 0; o >>= 1)
            s += __shfl_xor_sync(0xFFFFFFFFu, s, o);
        if (lane == 0) g_p[node] = s;
    }
}

// ---------------------------------------------------------------------------
// Kernel B: per-edge  z = p[src] + p[dst] + ea[e].w[64:80] + c;  sigmoid(z).
// Block prologue: warp0 -> w[64:80], warp1 -> c, warp2 -> dtype probe.
// Main loop: 4 block-strided edges per thread (coalesced; ~9 independent
// loads in flight hides the L2 latency of the random p gathers).
// ---------------------------------------------------------------------------
__global__ __launch_bounds__(EDGE_THREADS)
void edge_kernel(const void* __restrict__ ei_raw,
                 const float* __restrict__ ea,
                 const float* __restrict__ W1,
                 const float* __restrict__ b1,
                 const float* __restrict__ W2,
                 const float* __restrict__ b2,
                 float* __restrict__ out) {
    __shared__ float sw[D_EDGE];
    __shared__ float sc;
    __shared__ int   sis64;
    int t = threadIdx.x;
    int warp = t >> 5;
    int lane = t & 31;

    if (warp == 0) {
        float w2[5];
        #pragma unroll
        for (int k = 0; k < 5; k++) w2[k] = __ldg(W2 + lane + 32 * k);
        #pragma unroll
        for (int rr = 0; rr < D_EDGE; rr++) {
            float s = collapse_row(W1, w2, D_NODE + rr, lane);
            if (lane == 0) sw[rr] = s;
        }
    } else if (warp == 1) {
        // c = b1 . W2 + b2
        float s = 0.f;
        #pragma unroll
        for (int k = 0; k < 5; k++)
            s = fmaf(__ldg(b1 + lane + 32 * k), __ldg(W2 + lane + 32 * k), s);
        #pragma unroll
        for (int o = 16; o > 0; o >>= 1)
            s += __shfl_xor_sync(0xFFFFFFFFu, s, o);
        if (lane == 0) sc = s + __ldg(b2);
    } else if (warp == 2) {
        // Dtype probe: 32 entries as int64 all in [0,N_NODES) <=> truly int64
        // (int32 data would need 32 zero hi-words: P ~ 1e-160).
        const long long* ei64 = (const long long*)ei_raw;
        long long v = ei64[lane];
        int ok = (v >= 0 && v < N_NODES) ? 1 : 0;
        unsigned b = __ballot_sync(0xFFFFFFFFu, ok);
        if (lane == 0) sis64 = (b == 0xFFFFFFFFu) ? 1 : 0;
    }
    __syncthreads();

    float rw[D_EDGE];
    #pragma unroll
    for (int i = 0; i < D_EDGE; i++) rw[i] = sw[i];
    float c = sc;
    int is64 = sis64;

    int base = blockIdx.x * (EDGE_THREADS * EDGE_EPT) + t;

    int   srcs[EDGE_EPT], dsts[EDGE_EPT];
    int   valid[EDGE_EPT];
    #pragma unroll
    for (int k = 0; k < EDGE_EPT; k++) {
        int e = base + k * EDGE_THREADS;
        valid[k] = (e < N_EDGES);
        srcs[k] = dsts[k] = 0;
        if (valid[k]) {
            if (is64) {
                const long long* ei = (const long long*)ei_raw;
                srcs[k] = (int)__ldg(ei + e);
                dsts[k] = (int)__ldg(ei + (size_t)N_EDGES + e);
            } else {
                const int* ei = (const int*)ei_raw;
                srcs[k] = __ldg(ei + e);
                dsts[k] = __ldg(ei + (size_t)N_EDGES + e);
            }
        }
    }

    float ps[EDGE_EPT];
    float4 a0[EDGE_EPT], a1[EDGE_EPT], a2[EDGE_EPT], a3[EDGE_EPT];
    #pragma unroll
    for (int k = 0; k < EDGE_EPT; k++) {
        if (valid[k]) {
            int e = base + k * EDGE_THREADS;
            ps[k] = g_p[srcs[k]] + g_p[dsts[k]];
            const float4* a = (const float4*)(ea + (size_t)e * D_EDGE);
            a0[k] = __ldg(a + 0); a1[k] = __ldg(a + 1);
            a2[k] = __ldg(a + 2); a3[k] = __ldg(a + 3);
        }
    }

    #pragma unroll
    for (int k = 0; k < EDGE_EPT; k++) {
        if (valid[k]) {
            int e = base + k * EDGE_THREADS;
            float z = ps[k] + c;
            z += a0[k].x * rw[0]  + a0[k].y * rw[1]  + a0[k].z * rw[2]  + a0[k].w * rw[3];
            z += a1[k].x * rw[4]  + a1[k].y * rw[5]  + a1[k].z * rw[6]  + a1[k].w * rw[7];
            z += a2[k].x * rw[8]  + a2[k].y * rw[9]  + a2[k].z * rw[10] + a2[k].w * rw[11];
            z += a3[k].x * rw[12] + a3[k].y * rw[13] + a3[k].z * rw[14] + a3[k].w * rw[15];
            out[e] = 1.0f / (1.0f + __expf(-z));
        }
    }
}

extern "C" void kernel_launch(void* const* d_in, const int* in_sizes, int n_in,
                              void* d_out, int out_size) {
    // metadata order: x, edge_index, edge_attr, W1, b1, W2, b2
    const float* x  = (const float*)d_in[0];
    const void*  ei = d_in[1];
    const float* ea = (const float*)d_in[2];
    const float* W1 = (const float*)d_in[3];
    const float* b1 = (const float*)d_in[4];
    const float* W2 = (const float*)d_in[5];
    const float* b2 = (const float*)d_in[6];
    float* out = (float*)d_out;

    node_kernel<<<NODE_BLOCKS, NODE_THREADS>>>(x, W1, W2);
    edge_kernel<<<EDGE_BLOCKS, EDGE_THREADS>>>(ei, ea, W1, b1, W2, b2, out);
}

// round 6
// speedup vs baseline: 1.4706x; 1.0588x over previous
#include <cuda_runtime.h>
#include <math.h>

#define N_NODES 100000
#define N_EDGES 1000000
#define D_NODE 64
#define D_EDGE 16
#define NUM_PAR 80
#define HIDDEN 160

#define NODE_BLOCKS 592
#define NODE_THREADS 512          // 16 warps
#define EDGE_THREADS 256
#define EDGE_EPT 4                // edges per thread (block-strided)
#define EDGE_BLOCKS ((N_EDGES + EDGE_THREADS * EDGE_EPT - 1) / (EDGE_THREADS * EDGE_EPT))

// Scratch (allocation-free rule): node projections.
__device__ float g_p[N_NODES];

// Warp-cooperative collapsed weight for one row r of W1:
//   w[r] = sum_j W1[r,j] * W2[j], lane-parallel over j (5 strides of 32).
__device__ __forceinline__ float collapse_row(const float* __restrict__ W1,
                                              const float* __restrict__ w2reg,
                                              int r, int lane) {
    const float* row = W1 + r * HIDDEN;
    float s = 0.f;
    #pragma unroll
    for (int k = 0; k < 5; k++)
        s = fmaf(__ldg(row + lane + 32 * k), w2reg[k], s);
    #pragma unroll
    for (int o = 16; o > 0; o >>= 1)
        s += __shfl_xor_sync(0xFFFFFFFFu, s, o);
    return s;   // valid in all lanes
}

// ---------------------------------------------------------------------------
// Kernel A: node projections p[n] = dot(x[n], w[0:64]).
// Each block first recomputes w[0:64] (warps 0-7; W1 is L2-resident after
// wave 1), then grid-strides: one warp per node, lane reads float2
// (coalesced 256B/warp), shuffle reduction.
// ---------------------------------------------------------------------------
__global__ __launch_bounds__(NODE_THREADS)
void node_kernel(const float* __restrict__ x,
                 const float* __restrict__ W1,
                 const float* __restrict__ W2) {
    __shared__ float sw[D_NODE];
    int t = threadIdx.x;
    int warp = t >> 5;
    int lane = t & 31;

    if (warp < 8) {
        float w2[5];
        #pragma unroll
        for (int k = 0; k < 5; k++) w2[k] = __ldg(W2 + lane + 32 * k);
        #pragma unroll
        for (int rr = 0; rr < 8; rr++) {
            int r = warp * 8 + rr;
            float s = collapse_row(W1, w2, r, lane);
            if (lane == 0) sw[r] = s;
        }
    }
    __syncthreads();

    float rw0 = sw[lane * 2];
    float rw1 = sw[lane * 2 + 1];

    const int nwarps = NODE_BLOCKS * (NODE_THREADS / 32);
    for (int node = blockIdx.x * (NODE_THREADS / 32) + warp;
         node < N_NODES; node += nwarps) {
        float2 v = __ldg(((const float2*)x) + (size_t)node * 32 + lane);
        float s = fmaf(v.x, rw0, v.y * rw1);
        #pragma unroll
        for (int o = 16; o > 0; o >>= 1)
            s += __shfl_xor_sync(0xFFFFFFFFu, s, o);
        if (lane == 0) g_p[node] = s;
    }
}

// ---------------------------------------------------------------------------
// Kernel B: per-edge  z = p[src] + p[dst] + ea[e].w[64:80] + c;  sigmoid(z).
// Block prologue: warp0 -> w[64:80], warp1 -> c, warp2 -> dtype probe.
// Main body: 4 block-strided edges/thread. Register-lean: only indices and
// gathered p's are batched (long-latency, small); edge_attr float4s are
// consumed immediately per edge. __launch_bounds__(256,4) caps regs at 64
// -> 4 blocks/SM -> 32 warps/SM.
// ---------------------------------------------------------------------------
__global__ __launch_bounds__(EDGE_THREADS, 4)
void edge_kernel(const void* __restrict__ ei_raw,
                 const float* __restrict__ ea,
                 const float* __restrict__ W1,
                 const float* __restrict__ b1,
                 const float* __restrict__ W2,
                 const float* __restrict__ b2,
                 float* __restrict__ out) {
    __shared__ float sw[D_EDGE];
    __shared__ float sc;
    __shared__ int   sis64;
    int t = threadIdx.x;
    int warp = t >> 5;
    int lane = t & 31;

    if (warp == 0) {
        float w2[5];
        #pragma unroll
        for (int k = 0; k < 5; k++) w2[k] = __ldg(W2 + lane + 32 * k);
        #pragma unroll
        for (int rr = 0; rr < D_EDGE; rr++) {
            float s = collapse_row(W1, w2, D_NODE + rr, lane);
            if (lane == 0) sw[rr] = s;
        }
    } else if (warp == 1) {
        // c = b1 . W2 + b2
        float s = 0.f;
        #pragma unroll
        for (int k = 0; k < 5; k++)
            s = fmaf(__ldg(b1 + lane + 32 * k), __ldg(W2 + lane + 32 * k), s);
        #pragma unroll
        for (int o = 16; o > 0; o >>= 1)
            s += __shfl_xor_sync(0xFFFFFFFFu, s, o);
        if (lane == 0) sc = s + __ldg(b2);
    } else if (warp == 2) {
        // Dtype probe: 32 entries as int64 all in [0,N_NODES) <=> truly int64
        // (int32 data would need 32 zero hi-words: P ~ 1e-160).
        const long long* ei64 = (const long long*)ei_raw;
        long long v = ei64[lane];
        int ok = (v >= 0 && v < N_NODES) ? 1 : 0;
        unsigned b = __ballot_sync(0xFFFFFFFFu, ok);
        if (lane == 0) sis64 = (b == 0xFFFFFFFFu) ? 1 : 0;
    }
    __syncthreads();

    float c = sc;
    int is64 = sis64;
    int base = blockIdx.x * (EDGE_THREADS * EDGE_EPT) + t;

    // Batch the long-latency, register-cheap part: indices then p gathers.
    int srcs[EDGE_EPT], dsts[EDGE_EPT];
    #pragma unroll
    for (int k = 0; k < EDGE_EPT; k++) {
        int e = base + k * EDGE_THREADS;
        srcs[k] = dsts[k] = 0;
        if (e < N_EDGES) {
            if (is64) {
                const long long* ei = (const long long*)ei_raw;
                srcs[k] = (int)__ldg(ei + e);
                dsts[k] = (int)__ldg(ei + (size_t)N_EDGES + e);
            } else {
                const int* ei = (const int*)ei_raw;
                srcs[k] = __ldg(ei + e);
                dsts[k] = __ldg(ei + (size_t)N_EDGES + e);
            }
        }
    }

    float ps[EDGE_EPT];
    #pragma unroll
    for (int k = 0; k < EDGE_EPT; k++)
        ps[k] = g_p[srcs[k]] + g_p[dsts[k]];   // index 0 if invalid: harmless

    // Consume each edge immediately: edge_attr float4s live only per-iter.
    #pragma unroll
    for (int k = 0; k < EDGE_EPT; k++) {
        int e = base + k * EDGE_THREADS;
        if (e < N_EDGES) {
            const float4* a = (const float4*)(ea + (size_t)e * D_EDGE);
            float4 a0 = __ldg(a + 0);
            float4 a1 = __ldg(a + 1);
            float4 a2 = __ldg(a + 2);
            float4 a3 = __ldg(a + 3);
            float z = ps[k] + c;
            z += a0.x * sw[0]  + a0.y * sw[1]  + a0.z * sw[2]  + a0.w * sw[3];
            z += a1.x * sw[4]  + a1.y * sw[5]  + a1.z * sw[6]  + a1.w * sw[7];
            z += a2.x * sw[8]  + a2.y * sw[9]  + a2.z * sw[10] + a2.w * sw[11];
            z += a3.x * sw[12] + a3.y * sw[13] + a3.z * sw[14] + a3.w * sw[15];
            out[e] = 1.0f / (1.0f + __expf(-z));
        }
    }
}

extern "C" void kernel_launch(void* const* d_in, const int* in_sizes, int n_in,
                              void* d_out, int out_size) {
    // metadata order: x, edge_index, edge_attr, W1, b1, W2, b2
    const float* x  = (const float*)d_in[0];
    const void*  ei = d_in[1];
    const float* ea = (const float*)d_in[2];
    const float* W1 = (const float*)d_in[3];
    const float* b1 = (const float*)d_in[4];
    const float* W2 = (const float*)d_in[5];
    const float* b2 = (const float*)d_in[6];
    float* out = (float*)d_out;

    node_kernel<<<NODE_BLOCKS, NODE_THREADS>>>(x, W1, W2);
    edge_kernel<<<EDGE_BLOCKS, EDGE_THREADS>>>(ei, ea, W1, b1, W2, b2, out);
}

// round 7
// speedup vs baseline: 1.6667x; 1.1333x over previous
#include <cuda_runtime.h>
#include <math.h>

#define N_NODES 100000
#define N_EDGES 1000000
#define D_NODE 64
#define D_EDGE 16
#define NUM_PAR 80
#define HIDDEN 160

#define NODE_BLOCKS 592
#define NODE_THREADS 512          // 16 warps; 2 nodes per warp per iteration
#define EDGE_THREADS 256
#define EDGE_EPT 8                // edges per thread (block-strided)
#define EDGE_BLOCKS ((N_EDGES + EDGE_THREADS * EDGE_EPT - 1) / (EDGE_THREADS * EDGE_EPT))

// Scratch (allocation-free rule): node projections.
__device__ float g_p[N_NODES];

// Warp-cooperative collapsed weight for one row r of W1:
//   w[r] = sum_j W1[r,j] * W2[j], lane-parallel over j (5 strides of 32).
__device__ __forceinline__ float collapse_row(const float* __restrict__ W1,
                                              const float* __restrict__ w2reg,
                                              int r, int lane) {
    const float* row = W1 + r * HIDDEN;
    float s = 0.f;
    #pragma unroll
    for (int k = 0; k < 5; k++)
        s = fmaf(__ldg(row + lane + 32 * k), w2reg[k], s);
    #pragma unroll
    for (int o = 16; o > 0; o >>= 1)
        s += __shfl_xor_sync(0xFFFFFFFFu, s, o);
    return s;   // valid in all lanes
}

// ---------------------------------------------------------------------------
// Kernel A: node projections p[n] = dot(x[n], w[0:64]).
// Prologue: warps 0-7 recompute w[0:64] (W1 L2-resident after wave 1).
// Main loop: each warp handles 2 nodes/iter; lane loads one float4
// (512B/warp, coalesced), 16-lane shuffle-tree reduction.
// ---------------------------------------------------------------------------
__global__ __launch_bounds__(NODE_THREADS)
void node_kernel(const float* __restrict__ x,
                 const float* __restrict__ W1,
                 const float* __restrict__ W2) {
    __shared__ float sw[D_NODE];
    int t = threadIdx.x;
    int warp = t >> 5;
    int lane = t & 31;

    if (warp < 8) {
        float w2[5];
        #pragma unroll
        for (int k = 0; k < 5; k++) w2[k] = __ldg(W2 + lane + 32 * k);
        #pragma unroll
        for (int rr = 0; rr < 8; rr++) {
            int r = warp * 8 + rr;
            float s = collapse_row(W1, w2, r, lane);
            if (lane == 0) sw[r] = s;
        }
    }
    __syncthreads();

    int half = lane >> 4;        // 0 or 1: which of the warp's 2 nodes
    int q    = lane & 15;        // float4 slot within the node row
    float w0 = sw[q * 4 + 0];
    float w1 = sw[q * 4 + 1];
    float w2r = sw[q * 4 + 2];
    float w3 = sw[q * 4 + 3];

    const float4* x4 = (const float4*)x;
    const int stride = NODE_BLOCKS * (NODE_THREADS / 32) * 2;

    for (int node = blockIdx.x * ((NODE_THREADS / 32) * 2) + warp * 2 + half;
         node < N_NODES; node += stride) {
        float4 v = __ldg(x4 + (size_t)node * 16 + q);
        float s = fmaf(v.x, w0, fmaf(v.y, w1, fmaf(v.z, w2r, v.w * w3)));
        #pragma unroll
        for (int o = 8; o > 0; o >>= 1)
            s += __shfl_xor_sync(0xFFFFFFFFu, s, o);
        if (q == 0) g_p[node] = s;
    }
}

// ---------------------------------------------------------------------------
// Kernel B: per-edge  z = p[src] + p[dst] + ea[e].w[64:80] + c;  sigmoid(z).
// Prologue: warp0 -> w[64:80], warp1 -> c, warp2 -> dtype probe.
// Main body: 8 block-strided edges/thread. Indices loaded as 4-byte low
// words (valid for both int32 and int64<2^31 layouts, stride mult 1 or 2),
// then 16 p-gathers issued back-to-back (32 warps/SM x 16 = 512 in flight
// >> 250 needed for 1 wavefront/cyc L1 service). edge_attr consumed
// immediately per edge; w[64:80] lives in registers.
// ---------------------------------------------------------------------------
__global__ __launch_bounds__(EDGE_THREADS, 4)
void edge_kernel(const void* __restrict__ ei_raw,
                 const float* __restrict__ ea,
                 const float* __restrict__ W1,
                 const float* __restrict__ b1,
                 const float* __restrict__ W2,
                 const float* __restrict__ b2,
                 float* __restrict__ out) {
    __shared__ float sw[D_EDGE];
    __shared__ float sc;
    __shared__ int   smult;     // index stride multiplier: 1 (int32) or 2 (int64)
    int t = threadIdx.x;
    int warp = t >> 5;
    int lane = t & 31;

    if (warp == 0) {
        float w2[5];
        #pragma unroll
        for (int k = 0; k < 5; k++) w2[k] = __ldg(W2 + lane + 32 * k);
        #pragma unroll
        for (int rr = 0; rr < D_EDGE; rr++) {
            float s = collapse_row(W1, w2, D_NODE + rr, lane);
            if (lane == 0) sw[rr] = s;
        }
    } else if (warp == 1) {
        // c = b1 . W2 + b2
        float s = 0.f;
        #pragma unroll
        for (int k = 0; k < 5; k++)
            s = fmaf(__ldg(b1 + lane + 32 * k), __ldg(W2 + lane + 32 * k), s);
        #pragma unroll
        for (int o = 16; o > 0; o >>= 1)
            s += __shfl_xor_sync(0xFFFFFFFFu, s, o);
        if (lane == 0) sc = s + __ldg(b2);
    } else if (warp == 2) {
        // Dtype probe: 32 entries as int64 all in [0,N_NODES) <=> truly int64
        // (int32 data would need 32 zero hi-words: P ~ 1e-160).
        const long long* ei64 = (const long long*)ei_raw;
        long long v = ei64[lane];
        int ok = (v >= 0 && v < N_NODES) ? 1 : 0;
        unsigned b = __ballot_sync(0xFFFFFFFFu, ok);
        if (lane == 0) smult = (b == 0xFFFFFFFFu) ? 2 : 1;
    }
    __syncthreads();

    float rw[D_EDGE];
    #pragma unroll
    for (int i = 0; i < D_EDGE; i++) rw[i] = sw[i];
    const float c = sc;
    const int mult = smult;
    const int* eidx = (const int*)ei_raw;   // low 4 bytes hold the value (LE)

    const int base = blockIdx.x * (EDGE_THREADS * EDGE_EPT) + t;

    // Phase 1: all index loads (coalesced), batched.
    int srcs[EDGE_EPT], dsts[EDGE_EPT];
    #pragma unroll
    for (int k = 0; k < EDGE_EPT; k++) {
        int e = base + k * EDGE_THREADS;
        srcs[k] = dsts[k] = 0;
        if (e < N_EDGES) {
            srcs[k] = __ldg(eidx + (size_t)mult * e);
            dsts[k] = __ldg(eidx + (size_t)mult * ((size_t)N_EDGES + e));
        }
    }

    // Phase 2: all 16 scattered p-gathers issued back-to-back.
    float ps[EDGE_EPT];
    #pragma unroll
    for (int k = 0; k < EDGE_EPT; k++)
        ps[k] = g_p[srcs[k]] + g_p[dsts[k]];

    // Phase 3: per-edge streaming (edge_attr float4s live one edge at a time).
    #pragma unroll
    for (int k = 0; k < EDGE_EPT; k++) {
        int e = base + k * EDGE_THREADS;
        if (e < N_EDGES) {
            const float4* a = (const float4*)(ea + (size_t)e * D_EDGE);
            float4 a0 = __ldg(a + 0);
            float4 a1 = __ldg(a + 1);
            float4 a2 = __ldg(a + 2);
            float4 a3 = __ldg(a + 3);
            float z = ps[k] + c;
            z += a0.x * rw[0]  + a0.y * rw[1]  + a0.z * rw[2]  + a0.w * rw[3];
            z += a1.x * rw[4]  + a1.y * rw[5]  + a1.z * rw[6]  + a1.w * rw[7];
            z += a2.x * rw[8]  + a2.y * rw[9]  + a2.z * rw[10] + a2.w * rw[11];
            z += a3.x * rw[12] + a3.y * rw[13] + a3.z * rw[14] + a3.w * rw[15];
            out[e] = 1.0f / (1.0f + __expf(-z));
        }
    }
}

extern "C" void kernel_launch(void* const* d_in, const int* in_sizes, int n_in,
                              void* d_out, int out_size) {
    // metadata order: x, edge_index, edge_attr, W1, b1, W2, b2
    const float* x  = (const float*)d_in[0];
    const void*  ei = d_in[1];
    const float* ea = (const float*)d_in[2];
    const float* W1 = (const float*)d_in[3];
    const float* b1 = (const float*)d_in[4];
    const float* W2 = (const float*)d_in[5];
    const float* b2 = (const float*)d_in[6];
    float* out = (float*)d_out;

    node_kernel<<<NODE_BLOCKS, NODE_THREADS>>>(x, W1, W2);
    edge_kernel<<<EDGE_BLOCKS, EDGE_THREADS>>>(ei, ea, W1, b1, W2, b2, out);
}